// round 12
// baseline (speedup 1.0000x reference)
#include <cuda_runtime.h>
#include <cuda_fp16.h>
#include <cstdint>

#define B_  32
#define S_  2048
#define H_  512
#define E_  1024

#define KCH      64                 // K per chunk (64 fp16 = 128B rows)
#define NCHUNKS  (E_ / KCH)         // 16

// ---------------- device scratch (no allocations allowed) -------------------
__device__ __half g_Wth[H_ * E_];   // W_e^T as fp16: [h][e], K-major for B operand
__device__ float  g_dp8[8][B_][H_]; // dec_proj partials
__device__ float  g_part[4][B_][S_];// partial logits per h-chunk

// ---------------- helpers ---------------------------------------------------
__device__ __forceinline__ float fast_tanh(float x) {
    float e = __expf(2.f * x);
    return 1.f - __fdividef(2.f, e + 1.f);
}
__device__ __forceinline__ uint32_t smem_u32(const void* p) {
    uint32_t a;
    asm("{ .reg .u64 t; cvta.to.shared.u64 t, %1; cvt.u32.u64 %0, t; }" : "=r"(a) : "l"(p));
    return a;
}
__device__ __forceinline__ void cp16h(uint32_t sa, const __half* gp) {
    asm volatile("cp.async.cg.shared.global [%0], [%1], 16;"
                 :: "r"(sa), "l"(__cvta_generic_to_global((const void*)gp)) : "memory");
}
#define CP_COMMIT() asm volatile("cp.async.commit_group;" ::: "memory")

// ---------------- SMEM layout (dynamic, bytes) -------------------------------
#define SM_XS0   0                        // 128 x 144B = 18432
#define SM_XS1   18432
#define SM_WT0   36864                    // 128 x 144B
#define SM_WT1   55296
#define SM_DPS   73728                    // 128 f32
#define SM_VWS   74240                    // 128 f32
#define SM_PART  74752                    // 128*2 f32
#define SM_TOTAL 75776

// ---------------------------------------------------------------------------
// Kernel A (fused prep):
//   blocks [0,512):   W_e transpose+fp16:  g_Wth[h][e] = half(W_attn[512+e][h])
//   blocks [512,768): dec_proj partials, 8-way split over e (fp32)
// ---------------------------------------------------------------------------
__global__ __launch_bounds__(256) void prep(const float* __restrict__ W,
                                            const float* __restrict__ dh,
                                            const float* __restrict__ bias) {
    const int bid = blockIdx.x;
    const int tid = threadIdx.x;
    if (bid < 512) {
        __shared__ float t[32][33];
        const int h0 = (bid & 15) * 32, e0 = (bid >> 4) * 32;
        const int tx = tid & 31, ty = tid >> 5;
#pragma unroll
        for (int i = 0; i < 4; i++)
            t[ty + i * 8][tx] = W[(long)(H_ + e0 + ty + i * 8) * H_ + h0 + tx];
        __syncthreads();
#pragma unroll
        for (int i = 0; i < 4; i++)
            g_Wth[(long)(h0 + ty + i * 8) * E_ + e0 + tx] = __float2half_rn(t[tx][ty + i * 8]);
    } else {
        __shared__ float dhs[64];
        const int k = bid - 512;
        const int b = k >> 3, q = k & 7;
        const int e0 = q * 64;
        if (tid < 64) dhs[tid] = dh[b * H_ + e0 + tid];
        __syncthreads();
#pragma unroll
        for (int rep = 0; rep < 2; rep++) {
            const int h = tid + rep * 256;
            float acc = (q == 0) ? bias[h] : 0.f;
#pragma unroll 16
            for (int e = 0; e < 64; e++)
                acc = fmaf(dhs[e], W[(long)(e0 + e) * H_ + h], acc);
            g_dp8[q][b][h] = acc;
        }
    }
}

// ---------------------------------------------------------------------------
// Kernel B: fp16 HMMA main — 128(s) x 128(h) tile, K=1024, fused epilogue
// 8 warps: 4 along M (32 rows) x 2 along N (64 cols). m16n8k16.
// 2 CTAs/SM (reg-capped) so sync/latency gaps overlap across CTAs.
// ---------------------------------------------------------------------------
__global__ void __launch_bounds__(256, 2) attn_main(const float* __restrict__ enc,
                                                    const float* __restrict__ vw) {
    extern __shared__ char smem[];
    const int tid = threadIdx.x, warp = tid >> 5, lane = tid & 31;
    const int nch = blockIdx.x, stile = blockIdx.y, b = blockIdx.z;
    const int s0 = stile * 128, n0 = nch * 128;
    const int wm = warp & 3, wn = warp >> 2;

    const uint32_t sb = smem_u32(smem);
    const uint32_t xs_a[2] = { sb + SM_XS0, sb + SM_XS1 };
    const uint32_t wt_a[2] = { sb + SM_WT0, sb + SM_WT1 };
    float* dps  = (float*)(smem + SM_DPS);
    float* vws  = (float*)(smem + SM_VWS);
    float* part = (float*)(smem + SM_PART);

    if (tid < 128) {
        float a = 0.f;
#pragma unroll
        for (int q = 0; q < 8; q++) a += g_dp8[q][b][n0 + tid];
        dps[tid] = a;
        vws[tid] = vw[n0 + tid];
    }

    float d[2][8][4];
#pragma unroll
    for (int i = 0; i < 2; i++)
#pragma unroll
        for (int j = 0; j < 8; j++)
#pragma unroll
            for (int q = 0; q < 4; q++) d[i][j][q] = 0.f;

    const float*  encb = enc + ((long)b * S_ + s0) * E_;
    const __half* wtb  = g_Wth + (long)n0 * E_;

    auto ldw = [&](int kc, int bufi) {
        const int e0 = kc * KCH;
#pragma unroll
        for (int i = 0; i < 4; i++) {
            int g = tid + i * 256;
            int row = g >> 3, c = g & 7;
            cp16h(wt_a[bufi] + row * 144 + c * 16, wtb + (long)row * E_ + e0 + c * 8);
        }
    };
    // X: gmem fp32 -> fp16 smem, two batches of 4 float4 (peak 16 live regs)
    auto ldxstx = [&](int kc, int bufi) {
        const int e0 = kc * KCH;
#pragma unroll
        for (int half = 0; half < 2; half++) {
            float4 v[4];
#pragma unroll
            for (int i = 0; i < 4; i++) {
                int g = tid + (half * 4 + i) * 256;
                int row = g >> 4, c4 = (g & 15) * 4;
                v[i] = *(const float4*)(encb + (long)row * E_ + e0 + c4);
            }
#pragma unroll
            for (int i = 0; i < 4; i++) {
                int g = tid + (half * 4 + i) * 256;
                int row = g >> 4, c4 = (g & 15) * 4;
                __half2 h0 = __floats2half2_rn(v[i].x, v[i].y);
                __half2 h1 = __floats2half2_rn(v[i].z, v[i].w);
                uint32_t u0 = *(uint32_t*)&h0, u1 = *(uint32_t*)&h1;
                asm volatile("st.shared.v2.b32 [%0], {%1,%2};"
                             :: "r"(xs_a[bufi] + row * 144 + c4 * 2), "r"(u0), "r"(u1) : "memory");
            }
        }
    };

    // prologue: W(0) in flight
    ldw(0, 0); CP_COMMIT();

    for (int kc = 0; kc < NCHUNKS; kc++) {
        const int bufi = kc & 1;
        ldxstx(kc, bufi);                 // buf last read by MMA(kc-2): behind sync
        if (kc < NCHUNKS - 1) { ldw(kc + 1, bufi ^ 1); CP_COMMIT(); }
        if (kc < NCHUNKS - 1) asm volatile("cp.async.wait_group 1;" ::: "memory");
        else                  asm volatile("cp.async.wait_group 0;" ::: "memory");
        __syncthreads();

#pragma unroll
        for (int ks = 0; ks < 4; ks++) {
            const int kb = ks * 16;
            uint32_t Af[2][4], Bf[4][4];
#pragma unroll
            for (int mt = 0; mt < 2; mt++) {
                int arow = wm * 32 + mt * 16 + ((lane >> 3) & 1) * 8 + (lane & 7);
                int akh  = (lane >> 4) & 1;
                uint32_t aaddr = xs_a[bufi] + arow * 144 + (kb + akh * 8) * 2;
                asm volatile("ldmatrix.sync.aligned.m8n8.x4.shared.b16 {%0,%1,%2,%3}, [%4];"
                             : "=r"(Af[mt][0]), "=r"(Af[mt][1]),
                               "=r"(Af[mt][2]), "=r"(Af[mt][3]) : "r"(aaddr));
            }
#pragma unroll
            for (int nt2 = 0; nt2 < 4; nt2++) {
                int nr  = wn * 64 + nt2 * 16 + ((lane >> 4) & 1) * 8 + (lane & 7);
                int bkh = (lane >> 3) & 1;
                uint32_t baddr = wt_a[bufi] + nr * 144 + (kb + bkh * 8) * 2;
                asm volatile("ldmatrix.sync.aligned.m8n8.x4.shared.b16 {%0,%1,%2,%3}, [%4];"
                             : "=r"(Bf[nt2][0]), "=r"(Bf[nt2][1]),
                               "=r"(Bf[nt2][2]), "=r"(Bf[nt2][3]) : "r"(baddr));
            }
#pragma unroll
            for (int mt = 0; mt < 2; mt++)
#pragma unroll
                for (int nt = 0; nt < 8; nt++) {
                    uint32_t b0 = Bf[nt >> 1][(nt & 1) * 2 + 0];
                    uint32_t b1 = Bf[nt >> 1][(nt & 1) * 2 + 1];
                    asm volatile(
                        "mma.sync.aligned.m16n8k16.row.col.f32.f16.f16.f32 "
                        "{%0,%1,%2,%3}, {%4,%5,%6,%7}, {%8,%9}, {%0,%1,%2,%3};"
                        : "+f"(d[mt][nt][0]), "+f"(d[mt][nt][1]),
                          "+f"(d[mt][nt][2]), "+f"(d[mt][nt][3])
                        : "r"(Af[mt][0]), "r"(Af[mt][1]), "r"(Af[mt][2]), "r"(Af[mt][3]),
                          "r"(b0), "r"(b1));
                }
        }
        __syncthreads();
    }

    // Epilogue: energy = tanh(acc + dec_proj); partial = sum_h v_w[h] * energy
    float rs[2][2] = {{0.f, 0.f}, {0.f, 0.f}};
#pragma unroll
    for (int mt = 0; mt < 2; mt++)
#pragma unroll
        for (int nt = 0; nt < 8; nt++)
#pragma unroll
            for (int q = 0; q < 4; q++) {
                int col = wn * 64 + nt * 8 + (lane & 3) * 2 + (q & 1);
                rs[mt][q >> 1] += fast_tanh(d[mt][nt][q] + dps[col]) * vws[col];
            }
#pragma unroll
    for (int mt = 0; mt < 2; mt++)
#pragma unroll
        for (int rr = 0; rr < 2; rr++) {
            float v = rs[mt][rr];
            v += __shfl_xor_sync(0xffffffffu, v, 1);
            v += __shfl_xor_sync(0xffffffffu, v, 2);
            rs[mt][rr] = v;
        }
    if ((lane & 3) == 0) {
        int g = lane >> 2;
#pragma unroll
        for (int mt = 0; mt < 2; mt++)
#pragma unroll
            for (int rr = 0; rr < 2; rr++)
                part[(wm * 32 + mt * 16 + rr * 8 + g) * 2 + wn] = rs[mt][rr];
    }
    __syncthreads();
    if (tid < 128)
        g_part[nch][b][s0 + tid] = part[tid * 2 + 0] + part[tid * 2 + 1];
}

// ---------------------------------------------------------------------------
// Kernel C: sum n-chunk partials, mask, softmax over S
// ---------------------------------------------------------------------------
__global__ __launch_bounds__(256) void softmax_kernel(const int* __restrict__ mask,
                                                      float* __restrict__ out) {
    const int b = blockIdx.x;
    const int tid = threadIdx.x;
    __shared__ float red[8];
    float v[8];
#pragma unroll
    for (int i = 0; i < 8; i++) {
        int s = tid + i * 256;
        float x = g_part[0][b][s] + g_part[1][b][s] + g_part[2][b][s] + g_part[3][b][s];
        if (mask[b * S_ + s] == 0) x = -100000.0f;
        v[i] = x;
    }
    float m = v[0];
#pragma unroll
    for (int i = 1; i < 8; i++) m = fmaxf(m, v[i]);
#pragma unroll
    for (int o = 16; o > 0; o >>= 1) m = fmaxf(m, __shfl_xor_sync(0xffffffffu, m, o));
    if ((tid & 31) == 0) red[tid >> 5] = m;
    __syncthreads();
    m = red[0];
#pragma unroll
    for (int i = 1; i < 8; i++) m = fmaxf(m, red[i]);
    __syncthreads();
    float sum = 0.f;
#pragma unroll
    for (int i = 0; i < 8; i++) { v[i] = expf(v[i] - m); sum += v[i]; }
#pragma unroll
    for (int o = 16; o > 0; o >>= 1) sum += __shfl_xor_sync(0xffffffffu, sum, o);
    if ((tid & 31) == 0) red[tid >> 5] = sum;
    __syncthreads();
    sum = 0.f;
#pragma unroll
    for (int i = 0; i < 8; i++) sum += red[i];
    const float inv = 1.f / sum;
#pragma unroll
    for (int i = 0; i < 8; i++) out[b * S_ + tid + i * 256] = v[i] * inv;
}

// ---------------------------------------------------------------------------
extern "C" void kernel_launch(void* const* d_in, const int* in_sizes, int n_in,
                              void* d_out, int out_size) {
    const float* dh   = (const float*)d_in[0];   // decoder_hide (32,512)
    const float* enc  = (const float*)d_in[1];   // encoder_out (32,2048,1024)
    const int*   mask = (const int*)  d_in[2];   // mask (32,2048)
    const float* W    = (const float*)d_in[3];   // W_attn (1536,512)
    const float* bias = (const float*)d_in[4];   // b_attn (512,)
    const float* vw   = (const float*)d_in[5];   // v_w (512,)
    float* out = (float*)d_out;                  // (32,2048)

    cudaFuncSetAttribute(attn_main, cudaFuncAttributeMaxDynamicSharedMemorySize, SM_TOTAL);

    prep<<<768, 256>>>(W, dh, bias);
    attn_main<<<dim3(4, 16, 32), 256, SM_TOTAL>>>(enc, vw);
    softmax_kernel<<<B_, 256>>>(mask, out);
}